// round 3
// baseline (speedup 1.0000x reference)
#include <cuda_runtime.h>
#include <math.h>

// ---------------- problem constants ----------------
#define Bn 2
#define Hn 8
#define Ln 4096
#define Dm 512
#define dh 64
#define NBH (Bn*Hn)       // 16
#define SMAX 64           // upper bound on n_top (actual 45)

// ---------------- device scratch (no allocs allowed) ----------------
__device__ __align__(256) float g_q[(size_t)NBH*Ln*dh];   // [bh][l][d]
__device__ __align__(256) float g_k[(size_t)NBH*Ln*dh];
__device__ __align__(256) float g_v[(size_t)NBH*Ln*dh];
__device__ __align__(256) float g_m[(size_t)NBH*Ln];
__device__ int   g_top[NBH*SMAX];
__device__ __align__(256) float g_tot[(size_t)NBH*64*dh]; // chunk totals for cumsum

// ---------------- f32x2 helpers (Blackwell packed fp32) ----------------
__device__ __forceinline__ unsigned long long dup_f32(float x){
    unsigned long long r;
    asm("mov.b64 %0, {%1, %1};" : "=l"(r) : "f"(x));
    return r;
}
__device__ __forceinline__ unsigned long long ffma2(unsigned long long a,
                                                    unsigned long long b,
                                                    unsigned long long c){
    unsigned long long d;
    asm("fma.rn.f32x2 %0, %1, %2, %3;" : "=l"(d) : "l"(a), "l"(b), "l"(c));
    return d;
}
__device__ __forceinline__ float2 unpack2(unsigned long long v){
    float2 r;
    asm("mov.b64 {%0, %1}, %2;" : "=f"(r.x), "=f"(r.y) : "l"(v));
    return r;
}

// ---------------- K1: fp32 projection GEMM ----------------
// out[bh][l][d] = (X @ W + bias) reshaped; X:[B*L, D] row-major, W:[D, D] row-major.
#define BM 128
#define BN 128
#define BK 16

__global__ __launch_bounds__(256, 2)
void proj_kernel(const float* __restrict__ X, const float* __restrict__ W,
                 const float* __restrict__ bias, float* __restrict__ out)
{
    __shared__ __align__(16) float As[BK][BM];   // [k][m]
    __shared__ __align__(16) float Bs[BK][BN];   // [k][n]

    const int tid = threadIdx.x;
    const int tx = tid & 15, ty = tid >> 4;
    const int m0 = ty * 8, n0 = tx * 8;
    const int rowBase = blockIdx.y * BM;
    const int colBase = blockIdx.x * BN;

    unsigned long long acc[4][8];
    #pragma unroll
    for (int i = 0; i < 4; i++)
        #pragma unroll
        for (int j = 0; j < 8; j++) acc[i][j] = 0ull;

    for (int k0 = 0; k0 < Dm; k0 += BK) {
        // load A tile (128 rows x 16 k) transposed into As[k][m]
        #pragma unroll
        for (int t = 0; t < 2; t++) {
            int f = tid + t * 256;          // [0,512)
            int r = f >> 2;                 // row in tile
            int kq = (f & 3) * 4;           // k quad
            float4 v = *(const float4*)(X + (size_t)(rowBase + r) * Dm + k0 + kq);
            As[kq + 0][r] = v.x;
            As[kq + 1][r] = v.y;
            As[kq + 2][r] = v.z;
            As[kq + 3][r] = v.w;
        }
        // load B tile (16 k x 128 cols)
        #pragma unroll
        for (int t = 0; t < 2; t++) {
            int f = tid + t * 256;          // [0,512)
            int r = f >> 5;                 // k row [0,16)
            int cq = (f & 31) * 4;          // col quad
            float4 v = *(const float4*)(W + (size_t)(k0 + r) * Dm + colBase + cq);
            *(float4*)&Bs[r][cq] = v;
        }
        __syncthreads();

        #pragma unroll
        for (int k = 0; k < BK; k++) {
            // a: 8 consecutive m values -> 4 packed pairs, pre-packed in memory
            ulonglong2 a01 = *(const ulonglong2*)&As[k][m0];
            ulonglong2 a23 = *(const ulonglong2*)(&As[k][m0] + 4);
            unsigned long long ap[4] = { a01.x, a01.y, a23.x, a23.y };
            float4 b0 = *(const float4*)&Bs[k][n0];
            float4 b1 = *(const float4*)(&Bs[k][n0] + 4);
            unsigned long long bd[8] = {
                dup_f32(b0.x), dup_f32(b0.y), dup_f32(b0.z), dup_f32(b0.w),
                dup_f32(b1.x), dup_f32(b1.y), dup_f32(b1.z), dup_f32(b1.w)
            };
            #pragma unroll
            for (int i = 0; i < 4; i++)
                #pragma unroll
                for (int j = 0; j < 8; j++)
                    acc[i][j] = ffma2(ap[i], bd[j], acc[i][j]);
        }
        __syncthreads();
    }

    // epilogue: add bias, scatter to [bh][l][d] layout
    float bvv[8];
    #pragma unroll
    for (int j = 0; j < 8; j++) bvv[j] = bias[colBase + n0 + j];

    const int c0 = colBase + n0;
    const int h = c0 >> 6;
    const int d0 = c0 & 63;

    #pragma unroll
    for (int i = 0; i < 4; i++) {
        #pragma unroll
        for (int rr = 0; rr < 2; rr++) {
            int r = rowBase + m0 + 2 * i + rr;
            int b = r >> 12;
            int l = r & (Ln - 1);
            float* o = out + (((size_t)(b * Hn + h) * Ln + l) << 6) + d0;
            float vals[8];
            #pragma unroll
            for (int j = 0; j < 8; j++) {
                float2 f2 = unpack2(acc[i][j]);
                vals[j] = (rr == 0 ? f2.x : f2.y) + bvv[j];
            }
            *(float4*)o       = make_float4(vals[0], vals[1], vals[2], vals[3]);
            *(float4*)(o + 4) = make_float4(vals[4], vals[5], vals[6], vals[7]);
        }
    }
}

// ---------------- K2: sampled scores -> m ----------------
// one warp per (bh, l); lane covers 2 d-elements
__global__ __launch_bounds__(256)
void sample_score_kernel(const int* __restrict__ idxs, int S)
{
    int gid = blockIdx.x * 8 + (threadIdx.x >> 5);
    int lane = threadIdx.x & 31;
    int bh = gid >> 12;
    int l = gid & (Ln - 1);

    const float* q = g_q + ((size_t)bh << 18) + ((size_t)l << 6);
    float2 q2 = *(const float2*)(q + 2 * lane);
    const float* kb = g_k + ((size_t)bh << 18);

    float mx = -INFINITY, sm = 0.f;
    for (int s = 0; s < S; s++) {
        int idx = idxs[l * S + s];
        float2 k2 = *(const float2*)(kb + ((size_t)idx << 6) + 2 * lane);
        float p = q2.x * k2.x + q2.y * k2.y;
        #pragma unroll
        for (int o = 16; o; o >>= 1) p += __shfl_xor_sync(0xffffffffu, p, o);
        mx = fmaxf(mx, p);
        sm += p;
    }
    if (lane == 0)
        g_m[((size_t)bh << 12) + l] = mx - sm * (1.0f / (float)Ln);
}

// ---------------- K3: top-S argmax passes per (b,h) ----------------
__global__ __launch_bounds__(256)
void topk_kernel(int S)
{
    __shared__ float sm[Ln];
    __shared__ float rv[256];
    __shared__ int   ri[256];
    int bh = blockIdx.x, tid = threadIdx.x;

    for (int i = tid; i < Ln; i += 256) sm[i] = g_m[((size_t)bh << 12) + i];
    __syncthreads();

    for (int t = 0; t < S; t++) {
        float best = -INFINITY;
        int bi = Ln;
        for (int i = tid; i < Ln; i += 256) {
            float v = sm[i];
            if (v > best || (v == best && i < bi)) { best = v; bi = i; }
        }
        rv[tid] = best; ri[tid] = bi;
        __syncthreads();
        for (int o = 128; o; o >>= 1) {
            if (tid < o) {
                if (rv[tid + o] > rv[tid] ||
                    (rv[tid + o] == rv[tid] && ri[tid + o] < ri[tid])) {
                    rv[tid] = rv[tid + o]; ri[tid] = ri[tid + o];
                }
            }
            __syncthreads();
        }
        if (tid == 0) {
            g_top[bh * SMAX + t] = ri[0];
            sm[ri[0]] = -INFINITY;
        }
        __syncthreads();
    }
}

// ---------------- K5a: chunk-local cumsum of v, write local prefixes to out ----
__global__ void cumsum_part(float* __restrict__ out)
{
    int c = blockIdx.x, bh = blockIdx.y, d = threadIdx.x;
    int b = bh >> 3, h = bh & 7;
    const float* vb = g_v + ((size_t)bh << 18) + ((size_t)(c * 64) << 6) + d;
    float* ob = out + ((size_t)(b * Ln + c * 64)) * Dm + h * 64 + d;
    float run = 0.f;
    #pragma unroll 8
    for (int i = 0; i < 64; i++) {
        run += vb[(size_t)i << 6];
        ob[(size_t)i * Dm] = run;
    }
    g_tot[((size_t)bh * 64 + c) * 64 + d] = run;
}

// ---------------- K5b: exclusive scan of chunk totals ----------------
__global__ void cumsum_scan()
{
    int bh = blockIdx.x, d = threadIdx.x;
    float run = 0.f;
    for (int c = 0; c < 64; c++) {
        size_t ix = ((size_t)bh * 64 + c) * 64 + d;
        float t = g_tot[ix];
        g_tot[ix] = run;
        run += t;
    }
}

// ---------------- K5c: add chunk offsets ----------------
__global__ void cumsum_add(float* __restrict__ out)
{
    int c = blockIdx.x, bh = blockIdx.y, d = threadIdx.x;
    if (c == 0) return;
    float off = g_tot[((size_t)bh * 64 + c) * 64 + d];
    int b = bh >> 3, h = bh & 7;
    float* ob = out + ((size_t)(b * Ln + c * 64)) * Dm + h * 64 + d;
    #pragma unroll 8
    for (int i = 0; i < 64; i++) ob[(size_t)i * Dm] += off;
}

// ---------------- K4: full attention on selected rows + scatter ----------------
__global__ __launch_bounds__(256)
void attn_kernel(float* __restrict__ out, int S)
{
    __shared__ float qs[64];
    __shared__ float sc[Ln];
    __shared__ float red[256];
    __shared__ float vr[4][64];

    int bh = blockIdx.y, u = blockIdx.x;
    int tid = threadIdx.x;
    int lu = g_top[bh * SMAX + u];
    int nk = lu + 1;   // causal: keys 0..lu inclusive

    const float* qb = g_q + ((size_t)bh << 18) + ((size_t)lu << 6);
    if (tid < 64) qs[tid] = qb[tid];
    __syncthreads();

    int warp = tid >> 5, lane = tid & 31;
    const float* kb = g_k + ((size_t)bh << 18);
    float q0 = qs[2 * lane], q1 = qs[2 * lane + 1];
    const float scale = 0.125f;  // 1/sqrt(64)

    for (int key = warp; key < nk; key += 8) {
        float2 k2 = *(const float2*)(kb + ((size_t)key << 6) + 2 * lane);
        float p = q0 * k2.x + q1 * k2.y;
        #pragma unroll
        for (int o = 16; o; o >>= 1) p += __shfl_xor_sync(0xffffffffu, p, o);
        if (lane == 0) sc[key] = p * scale;
    }
    __syncthreads();

    // max over keys
    float mx = -INFINITY;
    for (int i = tid; i < nk; i += 256) mx = fmaxf(mx, sc[i]);
    red[tid] = mx; __syncthreads();
    for (int o = 128; o; o >>= 1) {
        if (tid < o) red[tid] = fmaxf(red[tid], red[tid + o]);
        __syncthreads();
    }
    mx = red[0]; __syncthreads();

    // exp + sum
    float z = 0.f;
    for (int i = tid; i < nk; i += 256) {
        float e = __expf(sc[i] - mx);
        sc[i] = e;
        z += e;
    }
    red[tid] = z; __syncthreads();
    for (int o = 128; o; o >>= 1) {
        if (tid < o) red[tid] += red[tid + o];
        __syncthreads();
    }
    z = red[0]; __syncthreads();

    // weighted sum over v: 4 key-groups x 64 d-lanes
    int g = tid >> 6, dl = tid & 63;
    const float* vb = g_v + ((size_t)bh << 18);
    float acc = 0.f;
    for (int key = g; key < nk; key += 4)
        acc += sc[key] * vb[((size_t)key << 6) + dl];
    vr[g][dl] = acc;
    __syncthreads();

    if (tid < 64) {
        float s = (vr[0][tid] + vr[1][tid]) + (vr[2][tid] + vr[3][tid]);
        int b = bh >> 3, h = bh & 7;
        out[((size_t)(b * Ln + lu)) * Dm + h * 64 + tid] = s / z;
    }
}

// ---------------- launch ----------------
extern "C" void kernel_launch(void* const* d_in, const int* in_sizes, int n_in,
                              void* d_out, int out_size)
{
    const float* queries = (const float*)d_in[0];
    const float* keys    = (const float*)d_in[1];
    const float* values  = (const float*)d_in[2];
    const float* Wq = (const float*)d_in[3];
    const float* bq = (const float*)d_in[4];
    const float* Wk = (const float*)d_in[5];
    const float* bk = (const float*)d_in[6];
    const float* Wv = (const float*)d_in[7];
    const float* bv = (const float*)d_in[8];
    const int*  idxs = (const int*)d_in[9];
    int S = in_sizes[9] / Ln;   // 45
    float* out = (float*)d_out;

    float *gq, *gk, *gv;
    cudaGetSymbolAddress((void**)&gq, g_q);
    cudaGetSymbolAddress((void**)&gk, g_k);
    cudaGetSymbolAddress((void**)&gv, g_v);

    dim3 gemmGrid(Dm / BN, (Bn * Ln) / BM);   // (4, 64)
    proj_kernel<<<gemmGrid, 256>>>(queries, Wq, bq, gq);
    proj_kernel<<<gemmGrid, 256>>>(keys,    Wk, bk, gk);
    proj_kernel<<<gemmGrid, 256>>>(values,  Wv, bv, gv);

    // cumsum of v into out (final layout)
    cumsum_part<<<dim3(64, NBH), 64>>>(out);
    cumsum_scan<<<NBH, 64>>>();
    cumsum_add<<<dim3(64, NBH), 64>>>(out);

    // sparse-attention measurement + selection
    sample_score_kernel<<<(NBH * Ln) / 8, 256>>>(idxs, S);
    topk_kernel<<<NBH, 256>>>(S);

    // full attention on selected rows, scatter into out
    attn_kernel<<<dim3(S, NBH), 256>>>(out, S);
}